// round 1
// baseline (speedup 1.0000x reference)
#include <cuda_runtime.h>
#include <math.h>

#define BB   8192
#define NX   2048
#define NH   512
#define NY   1024

// Scratch (device-global: no allocations allowed in kernel_launch)
__device__ float g_h[(size_t)BB * NH];     // 16 MB hidden activations
__device__ float g_hnorm[BB];              // ||h_i||^2
__device__ float g_wqnorm[NY];             // ||w_j||^2

// ---------------------------------------------------------------------------
// GEMM NT: C[m][n] = sum_k opA(A[m][k]) * B[n][k]
// A: [M,K] row-major, B: [N,K] row-major. All dims divisible by tiles.
// EPI==1: C = relu(acc + bias[n])           (hidden layer)
// EPI==2: C = -log1p(max(rown[m]-2*acc+coln[n], 0))   (quadratic logits, NU=1)
// ---------------------------------------------------------------------------
template<bool RELU_A, int EPI>
__global__ __launch_bounds__(256, 2)
void gemm_nt_kernel(const float* __restrict__ A, const float* __restrict__ Bm,
                    const float* __restrict__ bias,
                    const float* __restrict__ rown, const float* __restrict__ coln,
                    float* __restrict__ C, int M, int N, int K)
{
    constexpr int BM = 128, BN = 128, BK = 16;
    __shared__ float As[2][BK][BM];
    __shared__ float Bs[2][BK][BN];

    const int tid = threadIdx.x;
    const int bn  = blockIdx.x;        // N tile
    const int bm  = blockIdx.y;        // M tile
    const int tx  = tid & 15;          // 0..15  -> col group
    const int ty  = tid >> 4;          // 0..15  -> row group

    const float* Ab = A  + (size_t)bm * BM * K;
    const float* Bb = Bm + (size_t)bn * BN * K;

    const int lr = tid >> 2;           // 0..63 : row within tile
    const int lc = (tid & 3) << 2;     // 0,4,8,12 : k offset (float4)

    float acc[8][8];
    #pragma unroll
    for (int i = 0; i < 8; i++)
        #pragma unroll
        for (int j = 0; j < 8; j++) acc[i][j] = 0.f;

    const int KT = K / BK;

    // tile loader: gmem -> smem (transposed to [k][mn])
    auto load_tile = [&](int buf, int kt) {
        #pragma unroll
        for (int r = 0; r < 2; r++) {
            const int row = lr + r * 64;
            float4 va = *(const float4*)(Ab + (size_t)row * K + kt * BK + lc);
            if (RELU_A) {
                va.x = fmaxf(va.x, 0.f); va.y = fmaxf(va.y, 0.f);
                va.z = fmaxf(va.z, 0.f); va.w = fmaxf(va.w, 0.f);
            }
            As[buf][lc + 0][row] = va.x;
            As[buf][lc + 1][row] = va.y;
            As[buf][lc + 2][row] = va.z;
            As[buf][lc + 3][row] = va.w;

            float4 vb = *(const float4*)(Bb + (size_t)row * K + kt * BK + lc);
            Bs[buf][lc + 0][row] = vb.x;
            Bs[buf][lc + 1][row] = vb.y;
            Bs[buf][lc + 2][row] = vb.z;
            Bs[buf][lc + 3][row] = vb.w;
        }
    };

    auto compute_tile = [&](int buf) {
        #pragma unroll
        for (int k = 0; k < BK; k++) {
            float a[8], b[8];
            *(float4*)&a[0] = *(const float4*)&As[buf][k][ty * 8 + 0];
            *(float4*)&a[4] = *(const float4*)&As[buf][k][ty * 8 + 4];
            *(float4*)&b[0] = *(const float4*)&Bs[buf][k][tx * 8 + 0];
            *(float4*)&b[4] = *(const float4*)&Bs[buf][k][tx * 8 + 4];
            #pragma unroll
            for (int i = 0; i < 8; i++)
                #pragma unroll
                for (int j = 0; j < 8; j++)
                    acc[i][j] = fmaf(a[i], b[j], acc[i][j]);
        }
    };

    load_tile(0, 0);
    __syncthreads();
    for (int kt = 0; kt < KT - 1; ++kt) {
        const int cur = kt & 1;
        load_tile(cur ^ 1, kt + 1);   // writes other buffer: safe while reading cur
        compute_tile(cur);
        __syncthreads();              // next buffer ready; cur free to overwrite
    }
    compute_tile((KT - 1) & 1);

    // epilogue
    const int row0 = bm * BM + ty * 8;
    const int col0 = bn * BN + tx * 8;
    #pragma unroll
    for (int i = 0; i < 8; i++) {
        const int row = row0 + i;
        float* crow = C + (size_t)row * N + col0;
        #pragma unroll
        for (int j = 0; j < 8; j++) {
            float v = acc[i][j];
            if (EPI == 1) {
                v = fmaxf(v + bias[col0 + j], 0.f);
            } else { // EPI == 2
                float d = rown[row] - 2.f * v + coln[col0 + j];
                d = fmaxf(d, 0.f);
                v = -log1pf(d);      // NU=1: -(nu+1)/2 * log1p(d/nu) = -log1p(d)
            }
            crow[j] = v;
        }
    }
}

// ---------------------------------------------------------------------------
// Row squared-norm: one warp per row
// ---------------------------------------------------------------------------
__global__ void rownorm_kernel(const float* __restrict__ X, float* __restrict__ out,
                               int rows, int cols)
{
    const int warp = (blockIdx.x * blockDim.x + threadIdx.x) >> 5;
    const int lane = threadIdx.x & 31;
    if (warp >= rows) return;
    const float* r = X + (size_t)warp * cols;
    float s = 0.f;
    for (int c = lane; c < cols; c += 32) {
        const float v = r[c];
        s = fmaf(v, v, s);
    }
    #pragma unroll
    for (int o = 16; o; o >>= 1) s += __shfl_xor_sync(0xFFFFFFFFu, s, o);
    if (lane == 0) out[warp] = s;
}

// ---------------------------------------------------------------------------
// In-place per-row log-softmax normalization: t -= logsumexp(t)
// One block (256 threads) per row of NY=1024
// ---------------------------------------------------------------------------
__global__ __launch_bounds__(256)
void lse_kernel(float* __restrict__ T)
{
    __shared__ float rmax[8];
    __shared__ float rsum[8];
    float* t = T + (size_t)blockIdx.x * NY;
    const int tid  = threadIdx.x;
    const int lane = tid & 31;
    const int w    = tid >> 5;

    float v[4];
    float m = -INFINITY;
    #pragma unroll
    for (int i = 0; i < 4; i++) {
        v[i] = t[tid + i * 256];
        m = fmaxf(m, v[i]);
    }
    #pragma unroll
    for (int o = 16; o; o >>= 1) m = fmaxf(m, __shfl_xor_sync(0xFFFFFFFFu, m, o));
    if (lane == 0) rmax[w] = m;
    __syncthreads();
    m = rmax[0];
    #pragma unroll
    for (int i = 1; i < 8; i++) m = fmaxf(m, rmax[i]);

    float s = 0.f;
    #pragma unroll
    for (int i = 0; i < 4; i++) s += expf(v[i] - m);
    #pragma unroll
    for (int o = 16; o; o >>= 1) s += __shfl_xor_sync(0xFFFFFFFFu, s, o);
    if (lane == 0) rsum[w] = s;
    __syncthreads();
    float tot = rsum[0];
    #pragma unroll
    for (int i = 1; i < 8; i++) tot += rsum[i];

    const float lse = m + logf(tot);
    #pragma unroll
    for (int i = 0; i < 4; i++) t[tid + i * 256] = v[i] - lse;
}

// ---------------------------------------------------------------------------
extern "C" void kernel_launch(void* const* d_in, const int* in_sizes, int n_in,
                              void* d_out, int out_size)
{
    const float* x    = (const float*)d_in[0];   // [B, Nx]
    const float* W_fc = (const float*)d_in[1];   // [Nh, Nx]
    const float* b_fc = (const float*)d_in[2];   // [Nh]
    const float* W_q  = (const float*)d_in[3];   // [Ny, Nh]
    float* out = (float*)d_out;                  // [B, Ny]

    void* p;
    cudaGetSymbolAddress(&p, g_h);      float* h   = (float*)p;
    cudaGetSymbolAddress(&p, g_hnorm);  float* hn  = (float*)p;
    cudaGetSymbolAddress(&p, g_wqnorm); float* wqn = (float*)p;

    // 1) h = relu(relu(x) @ W_fc^T + b_fc)
    {
        dim3 grid(NH / 128, BB / 128);
        gemm_nt_kernel<true, 1><<<grid, 256>>>(x, W_fc, b_fc, nullptr, nullptr,
                                               h, BB, NH, NX);
    }
    // 2) row norms (independent)
    rownorm_kernel<<<(BB * 32 + 255) / 256, 256>>>(h, hn, BB, NH);
    rownorm_kernel<<<(NY * 32 + 255) / 256, 256>>>(W_q, wqn, NY, NH);

    // 3) t = -log1p(max(||h||^2 - 2 h@W_q^T + ||w||^2, 0))
    {
        dim3 grid(NY / 128, BB / 128);
        gemm_nt_kernel<false, 2><<<grid, 256>>>(h, W_q, nullptr, hn, wqn,
                                                out, BB, NY, NH);
    }
    // 4) log-softmax normalization per row
    lse_kernel<<<BB, 256>>>(out);
}

// round 3
// speedup vs baseline: 3.0025x; 3.0025x over previous
#include <cuda_runtime.h>
#include <math.h>
#include <stdint.h>

#define BB   8192
#define NX   2048
#define NH   512
#define NY   1024

// Scratch (no allocations allowed in kernel_launch)
__device__ float g_h[(size_t)BB * NH];     // hidden activations
__device__ float g_hnorm[BB];              // ||h_i||^2
__device__ float g_wqnorm[NY];             // ||w_j||^2

// ---------------------------------------------------------------------------
static __device__ __forceinline__ uint32_t smem_u32(const void* p) {
    uint32_t a;
    asm("{ .reg .u64 t; cvta.to.shared.u64 t, %1; cvt.u32.u64 %0, t; }"
        : "=r"(a) : "l"(p));
    return a;
}
static __device__ __forceinline__ uint32_t f2tf32(float f) {
    uint32_t o;
    asm("cvt.rna.tf32.f32 %0, %1;" : "=r"(o) : "f"(f));
    return o;
}

#define LDSM_X4(r0, r1, r2, r3, a)                                           \
    asm volatile("ldmatrix.sync.aligned.m8n8.x4.shared.b16 {%0,%1,%2,%3}, [%4];" \
                 : "=r"(r0), "=r"(r1), "=r"(r2), "=r"(r3) : "r"(a))

static __device__ __forceinline__ void mma8(float* c, const uint32_t* a,
                                            uint32_t b0, uint32_t b1) {
    asm volatile(
        "mma.sync.aligned.m16n8k8.row.col.f32.tf32.tf32.f32 "
        "{%0,%1,%2,%3}, {%4,%5,%6,%7}, {%8,%9}, {%0,%1,%2,%3};"
        : "+f"(c[0]), "+f"(c[1]), "+f"(c[2]), "+f"(c[3])
        : "r"(a[0]), "r"(a[1]), "r"(a[2]), "r"(a[3]), "r"(b0), "r"(b1));
}

// ---------------------------------------------------------------------------
// tf32 mma.sync GEMM-NT: C[m][n] = epi( sum_k opA(A[m][k]) * B[n][k] )
// CTA tile 128x128, BK=32, 8 warps (2m x 4n), warp tile 64x32, double buffer.
// EPI==1: C = relu(acc + prm[n])
// EPI==2: C = -log1p(max(rown[m] - 2*acc + prm[n], 0))
// ---------------------------------------------------------------------------
#define STAGE_BYTES 32768               // A 16KB + B 16KB
#define DSMEM_BYTES (2 * STAGE_BYTES)

template<bool RELU_A, int EPI>
__global__ __launch_bounds__(256, 2)
void tgemm(const float* __restrict__ A, const float* __restrict__ Bm,
           const float* __restrict__ prm, const float* __restrict__ rown,
           float* __restrict__ C, int M, int N, int K)
{
    extern __shared__ char smem[];
    const uint32_t sbase = smem_u32(smem);

    const int tid  = threadIdx.x;
    const int bn   = blockIdx.x, bm = blockIdx.y;
    const int warp = tid >> 5, lane = tid & 31;
    const int wm   = warp & 1;          // 0..1 : 64-row slice
    const int wn   = warp >> 1;         // 0..3 : 32-col slice

    // ---- loader indices: thread loads 4 rows x 16B (float4) per operand ----
    const int r0 = tid >> 3;            // 0..31
    const int c4 = tid & 7;             // 16B chunk in 128B row
    const int swc = (c4 ^ (r0 & 7)) * 16;  // swizzled byte offset of chunk

    // ---- ldmatrix addresses (byte offsets within tile) ----
    const int rm  = lane & 7;
    const int kh  = lane >> 4;           // k-half for A (j>>1)
    const int hB  = (lane >> 3) & 1;     // k-half for B (j&1)
    int rowA[4], rowB[2];
    #pragma unroll
    for (int mi = 0; mi < 4; mi++)
        rowA[mi] = wm * 64 + mi * 16 + ((lane >> 3) & 1) * 8 + rm;
    #pragma unroll
    for (int pp = 0; pp < 2; pp++)
        rowB[pp] = wn * 32 + pp * 16 + (lane >> 4) * 8 + rm;

    float acc[4][4][4];
    #pragma unroll
    for (int i = 0; i < 4; i++)
        #pragma unroll
        for (int j = 0; j < 4; j++)
            #pragma unroll
            for (int q = 0; q < 4; q++) acc[i][j][q] = 0.f;

    const int KT = K >> 5;

    auto load_stage = [&](int kt, int buf) {
        char* sa = smem + buf * STAGE_BYTES;
        char* sb = sa + 16384;
        const float* ag = A  + (size_t)(bm * 128 + r0) * K + kt * 32 + c4 * 4;
        const float* bg = Bm + (size_t)(bn * 128 + r0) * K + kt * 32 + c4 * 4;
        #pragma unroll
        for (int p = 0; p < 4; p++) {
            const int row = r0 + p * 32;
            float4 va = *(const float4*)(ag + (size_t)p * 32 * K);
            if (RELU_A) {
                va.x = fmaxf(va.x, 0.f); va.y = fmaxf(va.y, 0.f);
                va.z = fmaxf(va.z, 0.f); va.w = fmaxf(va.w, 0.f);
            }
            uint4 ta = { f2tf32(va.x), f2tf32(va.y), f2tf32(va.z), f2tf32(va.w) };
            *(uint4*)(sa + row * 128 + swc) = ta;

            float4 vb = *(const float4*)(bg + (size_t)p * 32 * K);
            uint4 tb = { f2tf32(vb.x), f2tf32(vb.y), f2tf32(vb.z), f2tf32(vb.w) };
            *(uint4*)(sb + row * 128 + swc) = tb;
        }
    };

    auto compute = [&](int buf) {
        const uint32_t Sa = sbase + buf * STAGE_BYTES;
        const uint32_t Sb = Sa + 16384;
        #pragma unroll
        for (int ks = 0; ks < 4; ks++) {
            uint32_t a[4][4], b[2][4];
            #pragma unroll
            for (int mi = 0; mi < 4; mi++) {
                const uint32_t addr = Sa + rowA[mi] * 128 + (((2*ks + kh) ^ rm) * 16);
                LDSM_X4(a[mi][0], a[mi][1], a[mi][2], a[mi][3], addr);
            }
            #pragma unroll
            for (int pp = 0; pp < 2; pp++) {
                const uint32_t addr = Sb + rowB[pp] * 128 + (((2*ks + hB) ^ rm) * 16);
                LDSM_X4(b[pp][0], b[pp][1], b[pp][2], b[pp][3], addr);
            }
            #pragma unroll
            for (int mi = 0; mi < 4; mi++)
                #pragma unroll
                for (int nj = 0; nj < 4; nj++)
                    mma8(acc[mi][nj], a[mi], b[nj >> 1][(nj & 1) * 2],
                         b[nj >> 1][(nj & 1) * 2 + 1]);
        }
    };

    load_stage(0, 0);
    for (int kt = 0; kt < KT; kt++) {
        __syncthreads();                    // stage kt resident; prev reads done
        if (kt + 1 < KT) load_stage(kt + 1, (kt + 1) & 1);
        compute(kt & 1);
    }

    // ---- epilogue ----
    const int gr0 = bm * 128 + wm * 64 + (lane >> 2);
    const int gc0 = bn * 128 + wn * 32 + (lane & 3) * 2;
    #pragma unroll
    for (int mi = 0; mi < 4; mi++) {
        #pragma unroll
        for (int half = 0; half < 2; half++) {
            const int row = gr0 + mi * 16 + half * 8;
            float rn = 0.f;
            if (EPI == 2) rn = rown[row];
            float* crow = C + (size_t)row * N;
            #pragma unroll
            for (int nj = 0; nj < 4; nj++) {
                const int col = gc0 + nj * 8;
                const float v0 = acc[mi][nj][half * 2 + 0];
                const float v1 = acc[mi][nj][half * 2 + 1];
                float2 o;
                if (EPI == 1) {
                    o.x = fmaxf(v0 + prm[col + 0], 0.f);
                    o.y = fmaxf(v1 + prm[col + 1], 0.f);
                } else {
                    float d0 = fmaxf(fmaf(-2.f, v0, rn + prm[col + 0]), 0.f);
                    float d1 = fmaxf(fmaf(-2.f, v1, rn + prm[col + 1]), 0.f);
                    o.x = -log1pf(d0);
                    o.y = -log1pf(d1);
                }
                *(float2*)(crow + col) = o;
            }
        }
    }
}

// ---------------------------------------------------------------------------
// Row squared-norm: one warp per row
// ---------------------------------------------------------------------------
__global__ void rownorm_kernel(const float* __restrict__ X, float* __restrict__ out,
                               int rows, int cols)
{
    const int warp = (blockIdx.x * blockDim.x + threadIdx.x) >> 5;
    const int lane = threadIdx.x & 31;
    if (warp >= rows) return;
    const float* r = X + (size_t)warp * cols;
    float s = 0.f;
    for (int c = lane; c < cols; c += 32) {
        const float v = r[c];
        s = fmaf(v, v, s);
    }
    #pragma unroll
    for (int o = 16; o; o >>= 1) s += __shfl_xor_sync(0xFFFFFFFFu, s, o);
    if (lane == 0) out[warp] = s;
}

// ---------------------------------------------------------------------------
// In-place per-row log-softmax: t -= logsumexp(t). One 256-thr block per row.
// ---------------------------------------------------------------------------
__global__ __launch_bounds__(256)
void lse_kernel(float* __restrict__ T)
{
    __shared__ float rmax[8];
    __shared__ float rsum[8];
    float* t = T + (size_t)blockIdx.x * NY;
    const int tid  = threadIdx.x;
    const int lane = tid & 31;
    const int w    = tid >> 5;

    float v[4];
    float m = -INFINITY;
    #pragma unroll
    for (int i = 0; i < 4; i++) {
        v[i] = t[tid + i * 256];
        m = fmaxf(m, v[i]);
    }
    #pragma unroll
    for (int o = 16; o; o >>= 1) m = fmaxf(m, __shfl_xor_sync(0xFFFFFFFFu, m, o));
    if (lane == 0) rmax[w] = m;
    __syncthreads();
    m = rmax[0];
    #pragma unroll
    for (int i = 1; i < 8; i++) m = fmaxf(m, rmax[i]);

    float s = 0.f;
    #pragma unroll
    for (int i = 0; i < 4; i++) s += expf(v[i] - m);
    #pragma unroll
    for (int o = 16; o; o >>= 1) s += __shfl_xor_sync(0xFFFFFFFFu, s, o);
    if (lane == 0) rsum[w] = s;
    __syncthreads();
    float tot = rsum[0];
    #pragma unroll
    for (int i = 1; i < 8; i++) tot += rsum[i];

    const float lse = m + logf(tot);
    #pragma unroll
    for (int i = 0; i < 4; i++) t[tid + i * 256] = v[i] - lse;
}

// ---------------------------------------------------------------------------
extern "C" void kernel_launch(void* const* d_in, const int* in_sizes, int n_in,
                              void* d_out, int out_size)
{
    const float* x    = (const float*)d_in[0];   // [B, Nx]
    const float* W_fc = (const float*)d_in[1];   // [Nh, Nx]
    const float* b_fc = (const float*)d_in[2];   // [Nh]
    const float* W_q  = (const float*)d_in[3];   // [Ny, Nh]
    float* out = (float*)d_out;                  // [B, Ny]

    void* p;
    cudaGetSymbolAddress(&p, g_h);      float* h   = (float*)p;
    cudaGetSymbolAddress(&p, g_hnorm);  float* hn  = (float*)p;
    cudaGetSymbolAddress(&p, g_wqnorm); float* wqn = (float*)p;

    cudaFuncSetAttribute(tgemm<true, 1>,  cudaFuncAttributeMaxDynamicSharedMemorySize, DSMEM_BYTES);
    cudaFuncSetAttribute(tgemm<false, 2>, cudaFuncAttributeMaxDynamicSharedMemorySize, DSMEM_BYTES);

    // 1) h = relu(relu(x) @ W_fc^T + b_fc)   [tf32 mma.sync]
    {
        dim3 grid(NH / 128, BB / 128);
        tgemm<true, 1><<<grid, 256, DSMEM_BYTES>>>(x, W_fc, b_fc, nullptr, h, BB, NH, NX);
    }
    // 2) row norms
    rownorm_kernel<<<(BB * 32 + 255) / 256, 256>>>(h, hn, BB, NH);
    rownorm_kernel<<<(NY * 32 + 255) / 256, 256>>>(W_q, wqn, NY, NH);

    // 3) t = -log1p(max(||h||^2 - 2 h@W_q^T + ||w||^2, 0))   [tf32 mma.sync]
    {
        dim3 grid(NY / 128, BB / 128);
        tgemm<false, 2><<<grid, 256, DSMEM_BYTES>>>(h, W_q, wqn, hn, out, BB, NY, NH);
    }
    // 4) log-softmax normalization per row
    lse_kernel<<<BB, 256>>>(out);
}

// round 4
// speedup vs baseline: 3.0467x; 1.0147x over previous
#include <cuda_runtime.h>
#include <math.h>
#include <stdint.h>

#define BB   8192
#define NX   2048
#define NH   512
#define NY   1024

// Scratch (no allocations allowed in kernel_launch)
__device__ float g_h[(size_t)BB * NH];     // hidden activations
__device__ float g_hnorm[BB];              // ||h_i||^2
__device__ float g_wqnorm[NY];             // ||w_j||^2

// ---------------------------------------------------------------------------
static __device__ __forceinline__ uint32_t smem_u32(const void* p) {
    uint32_t a;
    asm("{ .reg .u64 t; cvta.to.shared.u64 t, %1; cvt.u32.u64 %0, t; }"
        : "=r"(a) : "l"(p));
    return a;
}
static __device__ __forceinline__ uint32_t f2tf32(float f) {
    uint32_t o;
    asm("cvt.rna.tf32.f32 %0, %1;" : "=r"(o) : "f"(f));
    return o;
}

#define LDSM_X4(r0, r1, r2, r3, a)                                           \
    asm volatile("ldmatrix.sync.aligned.m8n8.x4.shared.b16 {%0,%1,%2,%3}, [%4];" \
                 : "=r"(r0), "=r"(r1), "=r"(r2), "=r"(r3) : "r"(a))

static __device__ __forceinline__ void mma8(float* c, const uint32_t* a,
                                            uint32_t b0, uint32_t b1) {
    asm volatile(
        "mma.sync.aligned.m16n8k8.row.col.f32.tf32.tf32.f32 "
        "{%0,%1,%2,%3}, {%4,%5,%6,%7}, {%8,%9}, {%0,%1,%2,%3};"
        : "+f"(c[0]), "+f"(c[1]), "+f"(c[2]), "+f"(c[3])
        : "r"(a[0]), "r"(a[1]), "r"(a[2]), "r"(a[3]), "r"(b0), "r"(b1));
}

// ---------------------------------------------------------------------------
// tf32 mma.sync GEMM-NT: C[m][n] = epi( sum_k opA(A[m][k]) * B[n][k] )
// CTA tile 128x128, BK=32, 8 warps (2m x 4n), warp tile 64x32, double buffer.
// EPI==1: C = relu(acc + prm[n])
// EPI==2: C = -log1p(max(rown[m] - 2*acc + prm[n], 0))
// ---------------------------------------------------------------------------
#define STAGE_BYTES 32768               // A 16KB + B 16KB
#define DSMEM_BYTES (2 * STAGE_BYTES)

template<bool RELU_A, int EPI>
__global__ __launch_bounds__(256, 2)
void tgemm(const float* __restrict__ A, const float* __restrict__ Bm,
           const float* __restrict__ prm, const float* __restrict__ rown,
           float* __restrict__ C, int M, int N, int K)
{
    extern __shared__ char smem[];
    const uint32_t sbase = smem_u32(smem);

    const int tid  = threadIdx.x;
    const int bn   = blockIdx.x, bm = blockIdx.y;
    const int warp = tid >> 5, lane = tid & 31;
    const int wm   = warp & 1;          // 0..1 : 64-row slice
    const int wn   = warp >> 1;         // 0..3 : 32-col slice

    // ---- loader indices: thread loads 4 rows x 16B (float4) per operand ----
    const int r0 = tid >> 3;            // 0..31
    const int c4 = tid & 7;             // 16B chunk in 128B row
    const int swc = (c4 ^ (r0 & 7)) * 16;  // swizzled byte offset of chunk

    // ---- ldmatrix addresses (byte offsets within tile) ----
    const int rm  = lane & 7;
    const int kh  = lane >> 4;           // k-half for A (j>>1)
    const int hB  = (lane >> 3) & 1;     // k-half for B (j&1)
    int rowA[4], rowB[2];
    #pragma unroll
    for (int mi = 0; mi < 4; mi++)
        rowA[mi] = wm * 64 + mi * 16 + ((lane >> 3) & 1) * 8 + rm;
    #pragma unroll
    for (int pp = 0; pp < 2; pp++)
        rowB[pp] = wn * 32 + pp * 16 + (lane >> 4) * 8 + rm;

    float acc[4][4][4];
    #pragma unroll
    for (int i = 0; i < 4; i++)
        #pragma unroll
        for (int j = 0; j < 4; j++)
            #pragma unroll
            for (int q = 0; q < 4; q++) acc[i][j][q] = 0.f;

    const int KT = K >> 5;

    auto load_stage = [&](int kt, int buf) {
        char* sa = smem + buf * STAGE_BYTES;
        char* sb = sa + 16384;
        const float* ag = A  + (size_t)(bm * 128 + r0) * K + kt * 32 + c4 * 4;
        const float* bg = Bm + (size_t)(bn * 128 + r0) * K + kt * 32 + c4 * 4;
        #pragma unroll
        for (int p = 0; p < 4; p++) {
            const int row = r0 + p * 32;
            float4 va = *(const float4*)(ag + (size_t)p * 32 * K);
            if (RELU_A) {
                va.x = fmaxf(va.x, 0.f); va.y = fmaxf(va.y, 0.f);
                va.z = fmaxf(va.z, 0.f); va.w = fmaxf(va.w, 0.f);
            }
            uint4 ta = { f2tf32(va.x), f2tf32(va.y), f2tf32(va.z), f2tf32(va.w) };
            *(uint4*)(sa + row * 128 + swc) = ta;

            float4 vb = *(const float4*)(bg + (size_t)p * 32 * K);
            uint4 tb = { f2tf32(vb.x), f2tf32(vb.y), f2tf32(vb.z), f2tf32(vb.w) };
            *(uint4*)(sb + row * 128 + swc) = tb;
        }
    };

    auto compute = [&](int buf) {
        const uint32_t Sa = sbase + buf * STAGE_BYTES;
        const uint32_t Sb = Sa + 16384;
        #pragma unroll
        for (int ks = 0; ks < 4; ks++) {
            uint32_t a[4][4], b[2][4];
            #pragma unroll
            for (int mi = 0; mi < 4; mi++) {
                const uint32_t addr = Sa + rowA[mi] * 128 + (((2*ks + kh) ^ rm) * 16);
                LDSM_X4(a[mi][0], a[mi][1], a[mi][2], a[mi][3], addr);
            }
            #pragma unroll
            for (int pp = 0; pp < 2; pp++) {
                const uint32_t addr = Sb + rowB[pp] * 128 + (((2*ks + hB) ^ rm) * 16);
                LDSM_X4(b[pp][0], b[pp][1], b[pp][2], b[pp][3], addr);
            }
            #pragma unroll
            for (int mi = 0; mi < 4; mi++)
                #pragma unroll
                for (int nj = 0; nj < 4; nj++)
                    mma8(acc[mi][nj], a[mi], b[nj >> 1][(nj & 1) * 2],
                         b[nj >> 1][(nj & 1) * 2 + 1]);
        }
    };

    load_stage(0, 0);
    for (int kt = 0; kt < KT; kt++) {
        __syncthreads();                    // stage kt resident; prev reads done
        if (kt + 1 < KT) load_stage(kt + 1, (kt + 1) & 1);
        compute(kt & 1);
    }

    // ---- epilogue ----
    const int gr0 = bm * 128 + wm * 64 + (lane >> 2);
    const int gc0 = bn * 128 + wn * 32 + (lane & 3) * 2;
    #pragma unroll
    for (int mi = 0; mi < 4; mi++) {
        #pragma unroll
        for (int half = 0; half < 2; half++) {
            const int row = gr0 + mi * 16 + half * 8;
            float rn = 0.f;
            if (EPI == 2) rn = rown[row];
            float* crow = C + (size_t)row * N;
            #pragma unroll
            for (int nj = 0; nj < 4; nj++) {
                const int col = gc0 + nj * 8;
                const float v0 = acc[mi][nj][half * 2 + 0];
                const float v1 = acc[mi][nj][half * 2 + 1];
                float2 o;
                if (EPI == 1) {
                    o.x = fmaxf(v0 + prm[col + 0], 0.f);
                    o.y = fmaxf(v1 + prm[col + 1], 0.f);
                } else {
                    float d0 = fmaxf(fmaf(-2.f, v0, rn + prm[col + 0]), 0.f);
                    float d1 = fmaxf(fmaf(-2.f, v1, rn + prm[col + 1]), 0.f);
                    o.x = -log1pf(d0);
                    o.y = -log1pf(d1);
                }
                *(float2*)(crow + col) = o;
            }
        }
    }
}

// ---------------------------------------------------------------------------
// Row squared-norm: one warp per row
// ---------------------------------------------------------------------------
__global__ void rownorm_kernel(const float* __restrict__ X, float* __restrict__ out,
                               int rows, int cols)
{
    const int warp = (blockIdx.x * blockDim.x + threadIdx.x) >> 5;
    const int lane = threadIdx.x & 31;
    if (warp >= rows) return;
    const float* r = X + (size_t)warp * cols;
    float s = 0.f;
    for (int c = lane; c < cols; c += 32) {
        const float v = r[c];
        s = fmaf(v, v, s);
    }
    #pragma unroll
    for (int o = 16; o; o >>= 1) s += __shfl_xor_sync(0xFFFFFFFFu, s, o);
    if (lane == 0) out[warp] = s;
}

// ---------------------------------------------------------------------------
// In-place per-row log-softmax: t -= logsumexp(t). One 256-thr block per row.
// ---------------------------------------------------------------------------
__global__ __launch_bounds__(256)
void lse_kernel(float* __restrict__ T)
{
    __shared__ float rmax[8];
    __shared__ float rsum[8];
    float* t = T + (size_t)blockIdx.x * NY;
    const int tid  = threadIdx.x;
    const int lane = tid & 31;
    const int w    = tid >> 5;

    float v[4];
    float m = -INFINITY;
    #pragma unroll
    for (int i = 0; i < 4; i++) {
        v[i] = t[tid + i * 256];
        m = fmaxf(m, v[i]);
    }
    #pragma unroll
    for (int o = 16; o; o >>= 1) m = fmaxf(m, __shfl_xor_sync(0xFFFFFFFFu, m, o));
    if (lane == 0) rmax[w] = m;
    __syncthreads();
    m = rmax[0];
    #pragma unroll
    for (int i = 1; i < 8; i++) m = fmaxf(m, rmax[i]);

    float s = 0.f;
    #pragma unroll
    for (int i = 0; i < 4; i++) s += expf(v[i] - m);
    #pragma unroll
    for (int o = 16; o; o >>= 1) s += __shfl_xor_sync(0xFFFFFFFFu, s, o);
    if (lane == 0) rsum[w] = s;
    __syncthreads();
    float tot = rsum[0];
    #pragma unroll
    for (int i = 1; i < 8; i++) tot += rsum[i];

    const float lse = m + logf(tot);
    #pragma unroll
    for (int i = 0; i < 4; i++) t[tid + i * 256] = v[i] - lse;
}

// ---------------------------------------------------------------------------
extern "C" void kernel_launch(void* const* d_in, const int* in_sizes, int n_in,
                              void* d_out, int out_size)
{
    const float* x    = (const float*)d_in[0];   // [B, Nx]
    const float* W_fc = (const float*)d_in[1];   // [Nh, Nx]
    const float* b_fc = (const float*)d_in[2];   // [Nh]
    const float* W_q  = (const float*)d_in[3];   // [Ny, Nh]
    float* out = (float*)d_out;                  // [B, Ny]

    void* p;
    cudaGetSymbolAddress(&p, g_h);      float* h   = (float*)p;
    cudaGetSymbolAddress(&p, g_hnorm);  float* hn  = (float*)p;
    cudaGetSymbolAddress(&p, g_wqnorm); float* wqn = (float*)p;

    cudaFuncSetAttribute(tgemm<true, 1>,  cudaFuncAttributeMaxDynamicSharedMemorySize, DSMEM_BYTES);
    cudaFuncSetAttribute(tgemm<false, 2>, cudaFuncAttributeMaxDynamicSharedMemorySize, DSMEM_BYTES);

    // 1) h = relu(relu(x) @ W_fc^T + b_fc)   [tf32 mma.sync]
    {
        dim3 grid(NH / 128, BB / 128);
        tgemm<true, 1><<<grid, 256, DSMEM_BYTES>>>(x, W_fc, b_fc, nullptr, h, BB, NH, NX);
    }
    // 2) row norms
    rownorm_kernel<<<(BB * 32 + 255) / 256, 256>>>(h, hn, BB, NH);
    rownorm_kernel<<<(NY * 32 + 255) / 256, 256>>>(W_q, wqn, NY, NH);

    // 3) t = -log1p(max(||h||^2 - 2 h@W_q^T + ||w||^2, 0))   [tf32 mma.sync]
    {
        dim3 grid(NY / 128, BB / 128);
        tgemm<false, 2><<<grid, 256, DSMEM_BYTES>>>(h, W_q, wqn, hn, out, BB, NY, NH);
    }
    // 4) log-softmax normalization per row
    lse_kernel<<<BB, 256>>>(out);
}